// round 3
// baseline (speedup 1.0000x reference)
#include <cuda_runtime.h>

#define BB    8
#define NMAX  128
#define HH    192
#define WW    256
#define INV_DOWN 0.125f
#define NBOX  (BB * NMAX)          // 1024 boxes
#define WARPS_PER_BLK 4
#define GRIDB (NBOX / WARPS_PER_BLK)   // 256 blocks

__device__ float2       g_data[NBOX];   // {err, valid} per box
__device__ unsigned int g_count = 0;

// Antiderivative of the bilinear hat kernel, clipped to [-1, 1]
__device__ __forceinline__ float hatP(float u) {
    u = fminf(1.0f, fmaxf(-1.0f, u));
    return (u <= 0.0f) ? 0.5f * (u + 1.0f) * (u + 1.0f)
                       : 0.5f + u - 0.5f * u * u;
}

__global__ __launch_bounds__(128)
void fused_kernel(const float* __restrict__ den,     // [B, 1, H, W]
                  const float* __restrict__ hboxes,  // [B, NMAX, 5]
                  const float* __restrict__ post,    // [B, NMAX, H, W]
                  float* __restrict__ out)
{
    const int t    = threadIdx.x;
    const int warp = t >> 5;
    const int lane = t & 31;
    const int bn   = blockIdx.x * WARPS_PER_BLK + warp;   // one warp = one box
    const int b    = bn >> 7;                             // bn / NMAX

    const float* box = hboxes + (size_t)bn * 5;
    const float lab = __ldg(box + 4);
    const float validf = (lab > 0.0f) ? 1.0f : 0.0f;

    float count = 0.0f;

    if (validf > 0.0f) {
        const float x1 = __ldg(box + 0) * INV_DOWN;
        const float y1 = __ldg(box + 1) * INV_DOWN;
        const float x2 = __ldg(box + 2) * INV_DOWN;
        const float y2 = __ldg(box + 3) * INV_DOWN;

        // Support of the hat weights (pad 1 each side; extras are exactly 0).
        const int ix0 = max(0, (int)floorf(x1) - 1);
        const int ix1 = min(WW - 1, (int)ceilf(x2) + 1);
        const int iy0 = max(0, (int)floorf(y1) - 1);
        const int iy1 = min(HH - 1, (int)ceilf(y2) + 1);
        const int nx = ix1 - ix0 + 1;   // <= 21
        const int ny = iy1 - iy0 + 1;   // <= 21

        // Per-lane x weight (register), per-lane y weight (to be shuffled).
        const bool inx = (lane < nx);
        float wxl = 0.0f;
        if (inx) {
            float fx = (float)(ix0 + lane);
            wxl = hatP(x2 - fx) - hatP(x1 - fx);
        }
        float wyl = 0.0f;
        if (lane < ny) {
            float fy = (float)(iy0 + lane);
            wyl = hatP(y2 - fy) - hatP(y1 - fy);
        }

        const float* denP  = den  + (size_t)b  * (HH * WW) + iy0 * WW + ix0 + lane;
        const float* postP = post + (size_t)bn * (HH * WW) + iy0 * WW + ix0 + lane;

        float acc = 0.0f;
        #pragma unroll 4
        for (int r = 0; r < ny; r++) {
            const float wyr = __shfl_sync(0xffffffffu, wyl, r);
            float d = 0.0f, p = 0.0f;
            if (inx) {
                d = __ldg(denP  + r * WW);
                p = __ldg(postP + r * WW);
            }
            acc += wyr * (d * p);
        }
        acc *= wxl;

        // Warp reduction
        #pragma unroll
        for (int o = 16; o > 0; o >>= 1)
            acc += __shfl_down_sync(0xffffffffu, acc, o);
        count = acc;   // valid in lane 0
    }

    if (lane == 0)
        g_data[bn] = make_float2(fabsf(count - 1.0f) * validf, validf);

    // Last-arriving block finalizes (deterministic: single fixed-order sum).
    __shared__ unsigned s_is_last;
    __syncthreads();
    if (t == 0) {
        __threadfence();
        unsigned v = atomicAdd(&g_count, 1u);
        s_is_last = (v == (unsigned)(GRIDB - 1)) ? 1u : 0u;
    }
    __syncthreads();

    if (s_is_last) {
        // 128 threads: 16 threads per image, each sums 8 entries.
        const int img = t >> 4;
        const int sub = t & 15;
        float e = 0.0f, v = 0.0f;
        #pragma unroll
        for (int k = 0; k < NMAX / 16; k++) {
            float2 d = __ldcg(&g_data[img * NMAX + sub + k * 16]);
            e += d.x;
            v += d.y;
        }
        #pragma unroll
        for (int o = 8; o > 0; o >>= 1) {
            e += __shfl_down_sync(0xffffffffu, e, o, 16);
            v += __shfl_down_sync(0xffffffffu, v, o, 16);
        }
        __shared__ float s_img[BB];
        if (sub == 0)
            s_img[img] = (v > 0.0f) ? (e / fmaxf(v, 1.0f)) : 0.0f;
        __syncthreads();
        if (t == 0) {
            float tot = 0.0f;
            #pragma unroll
            for (int i = 0; i < BB; i++) tot += s_img[i];
            out[0] = tot;
            g_count = 0;   // reset for next graph replay
        }
    }
}

extern "C" void kernel_launch(void* const* d_in, const int* in_sizes, int n_in,
                              void* d_out, int out_size)
{
    // metadata order: cls(0), reg(1), off(2), den(3), fboxes(4), hboxes(5),
    //                 ctr_masks(6), post_probs(7)
    const float* den    = (const float*)d_in[3];
    const float* hboxes = (const float*)d_in[5];
    const float* post   = (const float*)d_in[7];
    float* out = (float*)d_out;

    fused_kernel<<<GRIDB, 128>>>(den, hboxes, post, out);
}